// round 1
// baseline (speedup 1.0000x reference)
#include <cuda_runtime.h>
#include <math.h>

// ---------------------------------------------------------------------------
// HypRelEncoder (StarE/QUAD-style 2-layer qualifier-aware CompGCN), GB300.
//
// Key algebraic restructure vs reference:
//   segment_sum(norm * ((x[src]*rel_e) @ w), dst) == segment_sum(norm * (x[src]*rel_e), dst) @ w
//   segment_sum(q_msg, eid) @ w_q               == segment_sum(q_msg @ w_q, eid)
// so all big GEMMs run at node (200k) / qual (400k) granularity, not edge.
// ---------------------------------------------------------------------------

#define NE    200000
#define DIM   200
#define NEDGE 500000      // edges per direction
#define NQ    400000      // quals per direction
#define NR    200         // relation rows (2*NUM_REL)
#define NB    4096
#define QP    6

#define ALPHA 0.8f

// Output layout offsets (floats)
#define OFF_SUB 0
#define OFF_REL (NB*DIM)                    // 819200
#define OFF_QO  (2*NB*DIM)                  // 1638400
#define OFF_QR  (OFF_QO + NB*QP*DIM)        // 6553600
#define OFF_X   (OFF_QR + NB*QP*DIM)        // 11468800
#define OFF_R   (OFF_X + NE*DIM)            // 51468800

// ---------------- device scratch (no allocations allowed) ------------------
__device__ float g_qagg[(size_t)NEDGE * DIM];   // 400 MB, per-edge qual aggregate (projected)
__device__ float g_nbuf[(size_t)NE * DIM];      // 160 MB, per-direction node scatter buffer
__device__ float g_accum[(size_t)NE * DIM];     // 160 MB, loop + in_res accumulator
__device__ float g_x1[(size_t)NE * DIM];        // 160 MB, layer-1 output x
__device__ float g_r1[NR * DIM];                // layer-1 output r
__device__ float g_deg[2 * NE];
__device__ float g_dinv[2 * NE];
__device__ float g_norm[2 * NEDGE];

// ---------------- helpers ---------------------------------------------------

__global__ void k_zero(float* __restrict__ p, long n) {
    long i = ((long)blockIdx.x * blockDim.x + threadIdx.x) * 4;
    long st = (long)gridDim.x * blockDim.x * 4;
    float4 z = make_float4(0.f, 0.f, 0.f, 0.f);
    for (; i < n; i += st) *(float4*)(p + i) = z;
}

// deg[dir][src] += 1 over both directions (ei row0 = src for every column)
__global__ void k_deg(const int* __restrict__ ei, float* __restrict__ deg) {
    int i = blockIdx.x * blockDim.x + threadIdx.x;
    int st = gridDim.x * blockDim.x;
    for (; i < 2 * NEDGE; i += st) {
        int dir = (i >= NEDGE) ? 1 : 0;
        atomicAdd(&deg[dir * NE + ei[i]], 1.0f);
    }
}

__global__ void k_dinv(const float* __restrict__ deg, float* __restrict__ dinv) {
    int i = blockIdx.x * blockDim.x + threadIdx.x;
    int st = gridDim.x * blockDim.x;
    for (; i < 2 * NE; i += st) {
        float v = deg[i];
        dinv[i] = (v > 0.f) ? rsqrtf(v) : 0.f;
    }
}

__global__ void k_norm(const int* __restrict__ ei, const float* __restrict__ dinv,
                       float* __restrict__ nrm) {
    int i = blockIdx.x * blockDim.x + threadIdx.x;
    int st = gridDim.x * blockDim.x;
    for (; i < 2 * NEDGE; i += st) {
        int dir = (i >= NEDGE) ? 1 : 0;
        int s = ei[i];
        int d = ei[2 * NEDGE + i];      // row1 of edge_index
        nrm[i] = dinv[dir * NE + s] * dinv[dir * NE + d];
    }
}

// ---------------- fused-compose tiled SGEMM ---------------------------------
// C[rows,200] = compose(A)[rows,200] @ W[200,200], with mode-specific compose
// on load and mode-specific epilogue. BM=32 rows/block, 256 threads.
// Thread (ti=t>>5, tj=t&31) computes rows {ti,ti+8,ti+16,ti+24} x cols {tj+32c}.

enum { M_QUAL = 0, M_LOOP = 1, M_ACC = 2, M_FIN = 3, M_WRITE = 4 };

template <int MODE>
__global__ void __launch_bounds__(256)
k_gemm(const float* __restrict__ A,      // x table (QUAL/LOOP) or dense rows
       const float* __restrict__ relt,   // rel table (QUAL) / loop_rel (LOOP)
       const int*   __restrict__ qe,     // QUAL: entity index per row
       const int*   __restrict__ qr,     // QUAL: relation index per row
       const int*   __restrict__ qeid,   // QUAL: target edge per row
       const float* __restrict__ W,
       float*       __restrict__ out,
       const float* __restrict__ accin,  // FIN: previously accumulated (loop+in)
       const float* __restrict__ bias,   // FIN
       int nrows)
{
    __shared__ float As[32][DIM];
    int t = threadIdx.x;
    int row0 = blockIdx.x << 5;

    for (int l = t; l < 32 * DIM; l += 256) {
        int r = l / DIM, c = l - r * DIM;
        int gr = row0 + r;
        float v = 0.f;
        if (gr < nrows) {
            if (MODE == M_QUAL)
                v = A[(size_t)qe[gr] * DIM + c] * relt[(size_t)qr[gr] * DIM + c];
            else if (MODE == M_LOOP)
                v = A[(size_t)gr * DIM + c] * relt[c];
            else
                v = A[(size_t)gr * DIM + c];
        }
        As[r][c] = v;
    }
    __syncthreads();

    int ti = t >> 5, tj = t & 31;
    float acc[4][7];
#pragma unroll
    for (int r = 0; r < 4; r++)
#pragma unroll
        for (int c = 0; c < 7; c++) acc[r][c] = 0.f;

    for (int k = 0; k < DIM; k++) {
        float wv[7];
#pragma unroll
        for (int c = 0; c < 6; c++) wv[c] = W[k * DIM + tj + 32 * c];
        wv[6] = (tj < 8) ? W[k * DIM + tj + 192] : 0.f;
#pragma unroll
        for (int r = 0; r < 4; r++) {
            float a = As[ti + 8 * r][k];
#pragma unroll
            for (int c = 0; c < 7; c++) acc[r][c] = fmaf(a, wv[c], acc[r][c]);
        }
    }

#pragma unroll
    for (int r = 0; r < 4; r++) {
        int gr = row0 + ti + 8 * r;
        if (gr >= nrows) continue;
        int eid = (MODE == M_QUAL) ? qeid[gr] : 0;
#pragma unroll
        for (int c = 0; c < 7; c++) {
            int j = tj + 32 * c;
            if (j >= DIM) continue;
            float v = acc[r][c];
            if (MODE == M_QUAL)
                atomicAdd(&out[(size_t)eid * DIM + j], v);
            else if (MODE == M_ACC)
                out[(size_t)gr * DIM + j] += v;
            else if (MODE == M_FIN)
                out[(size_t)gr * DIM + j] =
                    tanhf((accin[(size_t)gr * DIM + j] + v) * (1.f / 3.f) + bias[j]);
            else
                out[(size_t)gr * DIM + j] = v;   // M_LOOP / M_WRITE
        }
    }
}

// ---------------- per-edge message scatter ----------------------------------
// nbuf[dst] += norm_e * x[src] * (ALPHA*rel[etype] + (1-ALPHA)*qagg[e])
__global__ void k_edge(const float* __restrict__ x, const float* __restrict__ relt,
                       const int* __restrict__ src, const int* __restrict__ dst,
                       const int* __restrict__ et, const float* __restrict__ nrm,
                       const float* __restrict__ qagg, float* __restrict__ nbuf)
{
    int warp = (blockIdx.x * blockDim.x + threadIdx.x) >> 5;
    int lane = threadIdx.x & 31;
    int nwarp = (gridDim.x * blockDim.x) >> 5;
    for (int e = warp; e < NEDGE; e += nwarp) {
        float nm = nrm[e];
        if (nm == 0.f) continue;
        int s = src[e], dd = dst[e], ty = et[e];
        const float* xr = x + (size_t)s * DIM;
        const float* rr = relt + (size_t)ty * DIM;
        const float* qr = qagg + (size_t)e * DIM;
        float* ob = nbuf + (size_t)dd * DIM;
        for (int c = lane; c < DIM; c += 32) {
            float v = nm * xr[c] * (ALPHA * rr[c] + (1.f - ALPHA) * qr[c]);
            atomicAdd(&ob[c], v);
        }
    }
}

// ---------------- final batched gathers -------------------------------------
__global__ void k_gather(const float* __restrict__ xf, const float* __restrict__ rf,
                         const int* __restrict__ ent_ix, const int* __restrict__ rel_ix,
                         const int* __restrict__ quals_ix, float* __restrict__ out)
{
    int warp = (blockIdx.x * blockDim.x + threadIdx.x) >> 5;
    int lane = threadIdx.x & 31;
    int nwarp = (gridDim.x * blockDim.x) >> 5;
    const int total = NB * 14;   // 1 sub + 1 rel + 6 qual_obj + 6 qual_rel rows per stmt
    for (int r = warp; r < total; r += nwarp) {
        int b = r / 14, s = r - b * 14;
        const float* srcp;
        float* dstp;
        if (s == 0)      { srcp = xf + (size_t)ent_ix[b] * DIM;  dstp = out + OFF_SUB + (size_t)b * DIM; }
        else if (s == 1) { srcp = rf + (size_t)rel_ix[b] * DIM;  dstp = out + OFF_REL + (size_t)b * DIM; }
        else if (s < 8)  { int p = s - 2;
                           srcp = xf + (size_t)quals_ix[b * 2 * QP + 2 * p + 1] * DIM;
                           dstp = out + OFF_QO + ((size_t)b * QP + p) * DIM; }
        else             { int p = s - 8;
                           srcp = rf + (size_t)quals_ix[b * 2 * QP + 2 * p] * DIM;
                           dstp = out + OFF_QR + ((size_t)b * QP + p) * DIM; }
        for (int c = lane; c < DIM; c += 32) dstp[c] = srcp[c];
    }
}

// ---------------------------------------------------------------------------

extern "C" void kernel_launch(void* const* d_in, const int* in_sizes, int n_in,
                              void* d_out, int out_size)
{
    // metadata (setup_inputs dict) order:
    const float* ent      = (const float*)d_in[0];
    const float* rel0     = (const float*)d_in[1];
    const float* w_in[2]   = {(const float*)d_in[2],  (const float*)d_in[7]};
    const float* w_out[2]  = {(const float*)d_in[3],  (const float*)d_in[8]};
    const float* w_loop[2] = {(const float*)d_in[4],  (const float*)d_in[9]};
    const float* w_rel[2]  = {(const float*)d_in[5],  (const float*)d_in[10]};
    const float* w_q[2]    = {(const float*)d_in[6],  (const float*)d_in[11]};
    const float* loop_rel[2] = {(const float*)d_in[12], (const float*)d_in[13]};
    const float* bias[2]   = {(const float*)d_in[14], (const float*)d_in[15]};
    const int* ei       = (const int*)d_in[16];
    const int* et       = (const int*)d_in[17];
    const int* qu       = (const int*)d_in[18];
    const int* ent_ix   = (const int*)d_in[19];
    const int* rel_ix   = (const int*)d_in[20];
    const int* quals_ix = (const int*)d_in[21];
    float* out = (float*)d_out;

    float *qagg, *nbuf, *accum, *x1, *r1, *deg, *dinv, *nrm;
    cudaGetSymbolAddress((void**)&qagg,  g_qagg);
    cudaGetSymbolAddress((void**)&nbuf,  g_nbuf);
    cudaGetSymbolAddress((void**)&accum, g_accum);
    cudaGetSymbolAddress((void**)&x1,    g_x1);
    cudaGetSymbolAddress((void**)&r1,    g_r1);
    cudaGetSymbolAddress((void**)&deg,   g_deg);
    cudaGetSymbolAddress((void**)&dinv,  g_dinv);
    cudaGetSymbolAddress((void**)&nrm,   g_norm);

    // ---- degree / symmetric norm (x-independent, but recomputed each call) ----
    k_zero<<<256, 256>>>(deg, 2L * NE);
    k_deg<<<2048, 256>>>(ei, deg);
    k_dinv<<<512, 256>>>(deg, dinv);
    k_norm<<<2048, 256>>>(ei, dinv, nrm);

    float* xf = out + OFF_X;
    float* rf = out + OFF_R;

    for (int L = 0; L < 2; L++) {
        const float* xin = L ? (const float*)x1 : ent;
        const float* rin = L ? (const float*)r1 : rel0;
        float* xout = L ? xf : x1;
        float* rout = L ? rf : r1;

        // accum = (x ⊙ loop_rel) @ w_loop   (plain write, no pre-zero needed)
        k_gemm<M_LOOP><<<(NE + 31) / 32, 256>>>(xin, loop_rel[L], 0, 0, 0,
                                                w_loop[L], accum, 0, 0, NE);
        for (int d = 0; d < 2; d++) {
            // qagg[e] = sum_{quals j: eid=e} (x[q_e]⊙rel[q_r]) @ w_q
            k_zero<<<4096, 256>>>(qagg, (long)NEDGE * DIM);
            k_gemm<M_QUAL><<<(NQ + 31) / 32, 256>>>(
                xin, rin,
                qu + 2 * NQ * 2 / 2 + d * NQ,           // q_e: quals row1 -> offset 800000
                qu + d * NQ,                            // q_r: quals row0
                qu + 4 * NQ + d * NQ,                   // q_eid: quals row2 -> offset 1600000
                w_q[L], qagg, 0, 0, NQ);
            // nbuf[dst] += norm * x[src] ⊙ (α rel[etype] + (1-α) qagg[e])
            k_zero<<<4096, 256>>>(nbuf, (long)NE * DIM);
            k_edge<<<4096, 256>>>(xin, rin,
                                  ei + d * NEDGE,                 // src (row0)
                                  ei + 2 * NEDGE + d * NEDGE,     // dst (row1)
                                  et + d * NEDGE,
                                  nrm + d * NEDGE, qagg, nbuf);
            if (d == 0)
                k_gemm<M_ACC><<<(NE + 31) / 32, 256>>>(nbuf, 0, 0, 0, 0,
                                                       w_in[L], accum, 0, 0, NE);
            else
                k_gemm<M_FIN><<<(NE + 31) / 32, 256>>>(nbuf, 0, 0, 0, 0,
                                                       w_out[L], xout, accum, bias[L], NE);
        }
        // r_out = r_in @ w_rel
        k_gemm<M_WRITE><<<(NR + 31) / 32, 256>>>(rin, 0, 0, 0, 0,
                                                 w_rel[L], rout, 0, 0, NR);
    }

    k_gather<<<7168, 256>>>(xf, rf, ent_ix, rel_ix, quals_ix, out);
}

// round 2
// speedup vs baseline: 2.3263x; 2.3263x over previous
#include <cuda_runtime.h>
#include <math.h>
#include <stdint.h>

// ---------------------------------------------------------------------------
// HypRelEncoder — round 2: tf32 tensor-core GEMMs + CSR gather (no atomics,
// no giant zero-fills).
//   qproj[j] = (x[q_e[j]] ⊙ rel[q_r[j]]) @ w_q          (plain-store GEMM)
//   nbuf[n]  = Σ_{e: dst=n} norm_e · x[src_e] ⊙ (α rel[et_e] + (1-α) Σ qproj)
//              (CSR gather, warp per node)
//   node-level GEMMs (loop / in / out) via tf32 mma.sync.
// ---------------------------------------------------------------------------

#define NE    200000
#define DIM   200
#define NEDGE 500000
#define NQ    400000
#define QROW  (2*NQ)       // 800000, row stride of quals array
#define NR    200
#define NB    4096
#define QP    6
#define ALPHA 0.8f

#define OFF_SUB 0
#define OFF_REL (NB*DIM)
#define OFF_QO  (2*NB*DIM)
#define OFF_QR  (OFF_QO + NB*QP*DIM)
#define OFF_X   (OFF_QR + NB*QP*DIM)
#define OFF_R   (OFF_X + NE*DIM)

// ---------------- device scratch -------------------------------------------
__device__ float g_qproj[(size_t)NQ * DIM];    // 320 MB
__device__ float g_nbuf[(size_t)NE * DIM];     // 160 MB
__device__ float g_accum[(size_t)NE * DIM];    // 160 MB
__device__ float g_x1[(size_t)NE * DIM];       // 160 MB
__device__ float g_r1[NR * DIM];
__device__ float g_dinv[2 * NE];
__device__ int gi_ecnt[2 * NE];
__device__ int gi_estart[2 * NE];
__device__ int gi_ecur[2 * NE];
__device__ int gi_elist[2 * NEDGE];
__device__ int gi_qcnt[2 * NEDGE];
__device__ int gi_qstart[2 * NEDGE];
__device__ int gi_qcur[2 * NEDGE];
__device__ int gi_qlist[2 * NQ];
__device__ int gi_part[1024];
__device__ int gi_psc[1024];

// ---------------- small helpers --------------------------------------------
__global__ void k_zero(float* __restrict__ p, long n) {
    long i = ((long)blockIdx.x * blockDim.x + threadIdx.x) * 4;
    long st = (long)gridDim.x * blockDim.x * 4;
    float4 z = make_float4(0.f, 0.f, 0.f, 0.f);
    for (; i < n; i += st) *(float4*)(p + i) = z;
}

// bucket = dir*NE + dst  (dst = edge_index row1)
__global__ void k_count_e(const int* __restrict__ ei, int* __restrict__ cnt) {
    int i = blockIdx.x * blockDim.x + threadIdx.x;
    int st = gridDim.x * blockDim.x;
    for (; i < 2 * NEDGE; i += st)
        atomicAdd(&cnt[((i >= NEDGE) ? NE : 0) + ei[2 * NEDGE + i]], 1);
}
__global__ void k_fill_e(const int* __restrict__ ei, int* __restrict__ cur,
                         int* __restrict__ list) {
    int i = blockIdx.x * blockDim.x + threadIdx.x;
    int st = gridDim.x * blockDim.x;
    for (; i < 2 * NEDGE; i += st) {
        int b = ((i >= NEDGE) ? NE : 0) + ei[2 * NEDGE + i];
        int pos = atomicAdd(&cur[b], 1);
        list[pos] = (i >= NEDGE) ? i - NEDGE : i;
    }
}
// bucket = dir*NEDGE + eid
__global__ void k_count_q(const int* __restrict__ qu, int* __restrict__ cnt) {
    int j = blockIdx.x * blockDim.x + threadIdx.x;
    int st = gridDim.x * blockDim.x;
    for (; j < 2 * NQ; j += st)
        atomicAdd(&cnt[((j >= NQ) ? NEDGE : 0) + qu[2 * QROW + j]], 1);
}
__global__ void k_fill_q(const int* __restrict__ qu, int* __restrict__ cur,
                         int* __restrict__ list) {
    int j = blockIdx.x * blockDim.x + threadIdx.x;
    int st = gridDim.x * blockDim.x;
    for (; j < 2 * NQ; j += st) {
        int b = ((j >= NQ) ? NEDGE : 0) + qu[2 * QROW + j];
        int pos = atomicAdd(&cur[b], 1);
        list[pos] = (j >= NQ) ? j - NQ : j;
    }
}

// deg for dir d = histogram of src in dir d = dst-counts of opposite dir
__global__ void k_dinv(const int* __restrict__ cnt, float* __restrict__ dinv) {
    int i = blockIdx.x * blockDim.x + threadIdx.x;
    int st = gridDim.x * blockDim.x;
    for (; i < 2 * NE; i += st) {
        int d = (i >= NE) ? 1 : 0;
        int n = i - d * NE;
        int c = cnt[(1 - d) * NE + n];
        dinv[i] = (c > 0) ? rsqrtf((float)c) : 0.f;
    }
}

// ---------------- two-level exclusive scan (n <= 1024*1024) ------------------
__global__ void k_scan1(const int* __restrict__ in, int* __restrict__ out,
                        int* __restrict__ part, int n) {
    __shared__ int s[1024];
    int t = threadIdx.x;
    int g = blockIdx.x * 1024 + t;
    int v = (g < n) ? in[g] : 0;
    s[t] = v;
    __syncthreads();
    for (int off = 1; off < 1024; off <<= 1) {
        int u = (t >= off) ? s[t - off] : 0;
        __syncthreads();
        s[t] += u;
        __syncthreads();
    }
    if (g < n) out[g] = s[t] - v;          // exclusive
    if (t == 1023 && part) part[blockIdx.x] = s[1023];
}
__global__ void k_scan_add(int* __restrict__ out, const int* __restrict__ psc, int n) {
    int g = blockIdx.x * 1024 + threadIdx.x;
    if (g < n) out[g] += psc[blockIdx.x];
}

// ---------------- tf32 tensor-core GEMM -------------------------------------
// C[rows,200] = compose(A)[rows,200] @ W[200,200]
// BM=64, BK=40 (5 chunks), BN=208 padded. 8 warps: 4 along M (16 rows each),
// 2 along N (104 cols = 13 frags of 8). Static smem 45 KB, 2 blocks/SM.

enum { M_QUAL = 0, M_LOOP = 1, M_ACC = 2, M_FIN = 3, M_WRITE = 4 };

#define BM 64
#define BK 40
#define BNP 208
#define AS_ST 41
#define WS_ST 216

__device__ __forceinline__ float tf32r(float x) {
    uint32_t u;
    asm("cvt.rna.tf32.f32 %0, %1;" : "=r"(u) : "f"(x));
    return __uint_as_float(u);
}
__device__ __forceinline__ void mma8(float* c, const uint32_t* a,
                                     uint32_t b0, uint32_t b1) {
    asm volatile(
        "mma.sync.aligned.m16n8k8.row.col.f32.tf32.tf32.f32 "
        "{%0,%1,%2,%3}, {%4,%5,%6,%7}, {%8,%9}, {%0,%1,%2,%3};"
        : "+f"(c[0]), "+f"(c[1]), "+f"(c[2]), "+f"(c[3])
        : "r"(a[0]), "r"(a[1]), "r"(a[2]), "r"(a[3]), "r"(b0), "r"(b1));
}

template <int MODE>
__global__ void __launch_bounds__(256, 2)
k_gemm(const float* __restrict__ A, const float* __restrict__ relt,
       const int* __restrict__ qe, const int* __restrict__ qr,
       const float* __restrict__ W, float* __restrict__ out,
       const float* __restrict__ accin, const float* __restrict__ bias,
       int nrows)
{
    __shared__ float As[BM * AS_ST];
    __shared__ float Ws[BK * WS_ST];
    int tid = threadIdx.x;
    int wid = tid >> 5, lane = tid & 31;
    int wm = wid >> 1, wn = wid & 1;
    int r4 = lane >> 2, kq = lane & 3;
    int row0 = blockIdx.x * BM;

    float acc[13][4];
#pragma unroll
    for (int f = 0; f < 13; f++) {
        acc[f][0] = acc[f][1] = acc[f][2] = acc[f][3] = 0.f;
    }

    for (int ch = 0; ch < 5; ch++) {
        __syncthreads();
        for (int l = tid; l < BM * BK; l += 256) {
            int r = l / BK, k = l - r * BK;
            int gr = row0 + r, gk = ch * BK + k;
            float v = 0.f;
            if (gr < nrows) {
                if (MODE == M_QUAL)
                    v = A[(size_t)qe[gr] * DIM + gk] * relt[(size_t)qr[gr] * DIM + gk];
                else if (MODE == M_LOOP)
                    v = A[(size_t)gr * DIM + gk] * relt[gk];
                else
                    v = A[(size_t)gr * DIM + gk];
            }
            As[r * AS_ST + k] = tf32r(v);
        }
        for (int l = tid; l < BK * BNP; l += 256) {
            int k = l / BNP, n = l - k * BNP;
            float v = (n < DIM) ? W[(size_t)(ch * BK + k) * DIM + n] : 0.f;
            Ws[k * WS_ST + n] = tf32r(v);
        }
        __syncthreads();

#pragma unroll
        for (int k8 = 0; k8 < 5; k8++) {
            int k0 = k8 * 8;
            int rb = wm * 16 + r4;
            uint32_t a[4];
            a[0] = __float_as_uint(As[rb * AS_ST + k0 + kq]);
            a[1] = __float_as_uint(As[(rb + 8) * AS_ST + k0 + kq]);
            a[2] = __float_as_uint(As[rb * AS_ST + k0 + 4 + kq]);
            a[3] = __float_as_uint(As[(rb + 8) * AS_ST + k0 + 4 + kq]);
#pragma unroll
            for (int f = 0; f < 13; f++) {
                int nb = wn * 104 + 8 * f + r4;
                uint32_t b0 = __float_as_uint(Ws[(k0 + kq) * WS_ST + nb]);
                uint32_t b1 = __float_as_uint(Ws[(k0 + 4 + kq) * WS_ST + nb]);
                mma8(acc[f], a, b0, b1);
            }
        }
    }

    int gr0 = row0 + wm * 16 + r4;
#pragma unroll
    for (int f = 0; f < 13; f++) {
        int col = wn * 104 + 8 * f + 2 * kq;
        if (col >= DIM) continue;   // only the (wn=1, f=12) frag is padding
#pragma unroll
        for (int half = 0; half < 2; half++) {
            int gr = gr0 + 8 * half;
            if (gr >= nrows) continue;
            size_t o = (size_t)gr * DIM + col;
            float v0 = acc[f][2 * half], v1 = acc[f][2 * half + 1];
            if (MODE == M_ACC) {
                out[o] += v0; out[o + 1] += v1;
            } else if (MODE == M_FIN) {
                out[o]     = tanhf((accin[o]     + v0) * (1.f / 3.f) + bias[col]);
                out[o + 1] = tanhf((accin[o + 1] + v1) * (1.f / 3.f) + bias[col + 1]);
            } else {
                out[o] = v0; out[o + 1] = v1;
            }
        }
    }
}

// ---------------- CSR gather aggregation -------------------------------------
// warp per dst node: nbuf[n] = Σ_edges norm · x[src] ⊙ (α rel[et] + (1-α) Σ qproj)
__global__ void __launch_bounds__(256)
k_agg(const float* __restrict__ x, const float* __restrict__ relt,
      const float* __restrict__ dinv,                        // + d*NE
      const int* __restrict__ src, const int* __restrict__ et,   // + d*NEDGE
      const int* __restrict__ e_start, const int* __restrict__ e_cnt,  // + d*NE
      const int* __restrict__ e_list,
      const int* __restrict__ q_start, const int* __restrict__ q_cnt,  // + d*NEDGE
      const int* __restrict__ q_list,
      const float* __restrict__ qproj, float* __restrict__ nbuf)
{
    int warp = (blockIdx.x * blockDim.x + threadIdx.x) >> 5;
    int lane = threadIdx.x & 31;
    if (warp >= NE) return;
    int n = warp;
    float acc[7];
#pragma unroll
    for (int c = 0; c < 7; c++) acc[c] = 0.f;

    float dn = dinv[n];
    if (dn != 0.f) {
        int beg = e_start[n], cnt = e_cnt[n];
        for (int idx = beg; idx < beg + cnt; idx++) {
            int e = e_list[idx];
            int s = src[e], ty = et[e];
            float nm = dn * dinv[s];
            const float* xr = x + (size_t)s * DIM;
            const float* rr = relt + (size_t)ty * DIM;
            float qs[7];
#pragma unroll
            for (int c = 0; c < 7; c++) qs[c] = 0.f;
            int qb = q_start[e], qc = q_cnt[e];
            for (int t = qb; t < qb + qc; t++) {
                const float* qp = qproj + (size_t)q_list[t] * DIM;
#pragma unroll
                for (int c = 0; c < 7; c++) {
                    int col = lane + 32 * c;
                    if (col < DIM) qs[c] += qp[col];
                }
            }
#pragma unroll
            for (int c = 0; c < 7; c++) {
                int col = lane + 32 * c;
                if (col < DIM)
                    acc[c] += nm * xr[col] * (ALPHA * rr[col] + (1.f - ALPHA) * qs[c]);
            }
        }
    }
#pragma unroll
    for (int c = 0; c < 7; c++) {
        int col = lane + 32 * c;
        if (col < DIM) nbuf[(size_t)n * DIM + col] = acc[c];
    }
}

// ---------------- final batched gathers --------------------------------------
__global__ void k_gather(const float* __restrict__ xf, const float* __restrict__ rf,
                         const int* __restrict__ ent_ix, const int* __restrict__ rel_ix,
                         const int* __restrict__ quals_ix, float* __restrict__ out)
{
    int warp = (blockIdx.x * blockDim.x + threadIdx.x) >> 5;
    int lane = threadIdx.x & 31;
    int nwarp = (gridDim.x * blockDim.x) >> 5;
    const int total = NB * 14;
    for (int r = warp; r < total; r += nwarp) {
        int b = r / 14, s = r - b * 14;
        const float* srcp;
        float* dstp;
        if (s == 0)      { srcp = xf + (size_t)ent_ix[b] * DIM;  dstp = out + OFF_SUB + (size_t)b * DIM; }
        else if (s == 1) { srcp = rf + (size_t)rel_ix[b] * DIM;  dstp = out + OFF_REL + (size_t)b * DIM; }
        else if (s < 8)  { int p = s - 2;
                           srcp = xf + (size_t)quals_ix[b * 2 * QP + 2 * p + 1] * DIM;
                           dstp = out + OFF_QO + ((size_t)b * QP + p) * DIM; }
        else             { int p = s - 8;
                           srcp = rf + (size_t)quals_ix[b * 2 * QP + 2 * p] * DIM;
                           dstp = out + OFF_QR + ((size_t)b * QP + p) * DIM; }
        for (int c = lane; c < DIM; c += 32) dstp[c] = srcp[c];
    }
}

// ---------------------------------------------------------------------------

extern "C" void kernel_launch(void* const* d_in, const int* in_sizes, int n_in,
                              void* d_out, int out_size)
{
    const float* ent        = (const float*)d_in[0];
    const float* rel0       = (const float*)d_in[1];
    const float* w_in[2]    = {(const float*)d_in[2],  (const float*)d_in[7]};
    const float* w_out[2]   = {(const float*)d_in[3],  (const float*)d_in[8]};
    const float* w_loop[2]  = {(const float*)d_in[4],  (const float*)d_in[9]};
    const float* w_rel[2]   = {(const float*)d_in[5],  (const float*)d_in[10]};
    const float* w_q[2]     = {(const float*)d_in[6],  (const float*)d_in[11]};
    const float* loop_rel[2]= {(const float*)d_in[12], (const float*)d_in[13]};
    const float* bias[2]    = {(const float*)d_in[14], (const float*)d_in[15]};
    const int* ei       = (const int*)d_in[16];
    const int* et       = (const int*)d_in[17];
    const int* qu       = (const int*)d_in[18];
    const int* ent_ix   = (const int*)d_in[19];
    const int* rel_ix   = (const int*)d_in[20];
    const int* quals_ix = (const int*)d_in[21];
    float* out = (float*)d_out;

    float *qproj, *nbuf, *accum, *x1, *r1, *dinv;
    int *ecnt, *estart, *ecur, *elist, *qcnt, *qstart, *qcur, *qlist, *part, *psc;
    cudaGetSymbolAddress((void**)&qproj,  g_qproj);
    cudaGetSymbolAddress((void**)&nbuf,   g_nbuf);
    cudaGetSymbolAddress((void**)&accum,  g_accum);
    cudaGetSymbolAddress((void**)&x1,     g_x1);
    cudaGetSymbolAddress((void**)&r1,     g_r1);
    cudaGetSymbolAddress((void**)&dinv,   g_dinv);
    cudaGetSymbolAddress((void**)&ecnt,   gi_ecnt);
    cudaGetSymbolAddress((void**)&estart, gi_estart);
    cudaGetSymbolAddress((void**)&ecur,   gi_ecur);
    cudaGetSymbolAddress((void**)&elist,  gi_elist);
    cudaGetSymbolAddress((void**)&qcnt,   gi_qcnt);
    cudaGetSymbolAddress((void**)&qstart, gi_qstart);
    cudaGetSymbolAddress((void**)&qcur,   gi_qcur);
    cudaGetSymbolAddress((void**)&qlist,  gi_qlist);
    cudaGetSymbolAddress((void**)&part,   gi_part);
    cudaGetSymbolAddress((void**)&psc,    gi_psc);

    // ---- CSR build (edges by dst, quals by eid) ----
    k_zero<<<256, 256>>>((float*)ecnt, 2L * NE);
    k_zero<<<512, 256>>>((float*)qcnt, 2L * NEDGE);
    k_count_e<<<2048, 256>>>(ei, ecnt);
    k_count_q<<<2048, 256>>>(qu, qcnt);

    int nbE = (2 * NE + 1023) / 1024;      // 391
    k_scan1<<<nbE, 1024>>>(ecnt, estart, part, 2 * NE);
    k_scan1<<<1, 1024>>>(part, psc, (int*)0, nbE);
    k_scan_add<<<nbE, 1024>>>(estart, psc, 2 * NE);
    cudaMemcpyAsync(ecur, estart, 2L * NE * sizeof(int), cudaMemcpyDeviceToDevice, 0);
    k_fill_e<<<2048, 256>>>(ei, ecur, elist);

    int nbQ = (2 * NEDGE + 1023) / 1024;   // 977
    k_scan1<<<nbQ, 1024>>>(qcnt, qstart, part, 2 * NEDGE);
    k_scan1<<<1, 1024>>>(part, psc, (int*)0, nbQ);
    k_scan_add<<<nbQ, 1024>>>(qstart, psc, 2 * NEDGE);
    cudaMemcpyAsync(qcur, qstart, 2L * NEDGE * sizeof(int), cudaMemcpyDeviceToDevice, 0);
    k_fill_q<<<2048, 256>>>(qu, qcur, qlist);

    k_dinv<<<512, 256>>>(ecnt, dinv);

    float* xf = out + OFF_X;
    float* rf = out + OFF_R;

    for (int L = 0; L < 2; L++) {
        const float* xin = L ? (const float*)x1 : ent;
        const float* rin = L ? (const float*)r1 : rel0;
        float* xout = L ? xf : x1;
        float* rout = L ? rf : r1;

        // accum = (x ⊙ loop_rel) @ w_loop
        k_gemm<M_LOOP><<<(NE + BM - 1) / BM, 256>>>(xin, loop_rel[L], 0, 0,
                                                    w_loop[L], accum, 0, 0, NE);
        for (int d = 0; d < 2; d++) {
            // qproj[j] = (x[q_e]⊙rel[q_r]) @ w_q   (plain store)
            k_gemm<M_QUAL><<<(NQ + BM - 1) / BM, 256>>>(
                xin, rin,
                qu + QROW + d * NQ,      // q_e (row 1)
                qu + d * NQ,             // q_r (row 0)
                w_q[L], qproj, 0, 0, NQ);
            // CSR gather into nbuf (no zeroing, no atomics)
            k_agg<<<(NE * 32 + 255) / 256, 256>>>(
                xin, rin, dinv + (size_t)d * NE,
                ei + (size_t)d * NEDGE,                // src row
                et + (size_t)d * NEDGE,
                estart + (size_t)d * NE, ecnt + (size_t)d * NE, elist,
                qstart + (size_t)d * NEDGE, qcnt + (size_t)d * NEDGE, qlist,
                qproj, nbuf);
            if (d == 0)
                k_gemm<M_ACC><<<(NE + BM - 1) / BM, 256>>>(nbuf, 0, 0, 0,
                                                           w_in[L], accum, 0, 0, NE);
            else
                k_gemm<M_FIN><<<(NE + BM - 1) / BM, 256>>>(nbuf, 0, 0, 0,
                                                           w_out[L], xout, accum,
                                                           bias[L], NE);
        }
        k_gemm<M_WRITE><<<(NR + BM - 1) / BM, 256>>>(rin, 0, 0, 0,
                                                     w_rel[L], rout, 0, 0, NR);
    }

    k_gather<<<7168, 256>>>(xf, rf, ent_ix, rel_ix, quals_ix, out);
}

// round 5
// speedup vs baseline: 3.1005x; 1.3328x over previous
#include <cuda_runtime.h>
#include <math.h>
#include <stdint.h>

// ---------------------------------------------------------------------------
// HypRelEncoder — round 4 (re-bench of round-3 design after infra failure):
//  * one K=600 fused output GEMM per layer (in|out|loop stacked) -> no accum buf
//  * one 800k-row qual GEMM + one both-direction CSR aggregation per layer
//  * float4 gathers everywhere
// ---------------------------------------------------------------------------

#define NE    200000
#define DIM   200
#define D4    50          // DIM / 4
#define NEDGE 500000
#define NQ    400000
#define QROW  (2*NQ)      // row stride of quals array (800000)
#define NR    200
#define NB    4096
#define QP    6
#define ALPHA 0.8f

#define OFF_SUB 0
#define OFF_REL (NB*DIM)
#define OFF_QO  (2*NB*DIM)
#define OFF_QR  (OFF_QO + NB*QP*DIM)
#define OFF_X   (OFF_QR + NB*QP*DIM)
#define OFF_R   (OFF_X + NE*DIM)

// ---------------- device scratch -------------------------------------------
__device__ float g_qproj[(size_t)QROW * DIM];    // 640 MB (both dirs)
__device__ float g_nin [(size_t)NE * DIM];       // 160 MB
__device__ float g_nout[(size_t)NE * DIM];       // 160 MB
__device__ float g_x1  [(size_t)NE * DIM];       // 160 MB
__device__ float g_r1[NR * DIM];
__device__ float g_dinv[2 * NE];
__device__ int gi_ecnt[2 * NE];
__device__ int gi_estart[2 * NE];
__device__ int gi_ecur[2 * NE];
__device__ int gi_elist[2 * NEDGE];
__device__ int gi_qcnt[2 * NEDGE];
__device__ int gi_qstart[2 * NEDGE];
__device__ int gi_qcur[2 * NEDGE];
__device__ int gi_qlist[2 * NQ];
__device__ int gi_part[1024];
__device__ int gi_psc[1024];

// ---------------- small helpers --------------------------------------------
__global__ void k_zero(float* __restrict__ p, long n) {
    long i = ((long)blockIdx.x * blockDim.x + threadIdx.x) * 4;
    long st = (long)gridDim.x * blockDim.x * 4;
    float4 z = make_float4(0.f, 0.f, 0.f, 0.f);
    for (; i < n; i += st) *(float4*)(p + i) = z;
}

__global__ void k_count_e(const int* __restrict__ ei, int* __restrict__ cnt) {
    int i = blockIdx.x * blockDim.x + threadIdx.x;
    int st = gridDim.x * blockDim.x;
    for (; i < 2 * NEDGE; i += st)
        atomicAdd(&cnt[((i >= NEDGE) ? NE : 0) + ei[2 * NEDGE + i]], 1);
}
__global__ void k_fill_e(const int* __restrict__ ei, int* __restrict__ cur,
                         int* __restrict__ list) {
    int i = blockIdx.x * blockDim.x + threadIdx.x;
    int st = gridDim.x * blockDim.x;
    for (; i < 2 * NEDGE; i += st) {
        int b = ((i >= NEDGE) ? NE : 0) + ei[2 * NEDGE + i];
        int pos = atomicAdd(&cur[b], 1);
        list[pos] = (i >= NEDGE) ? i - NEDGE : i;      // local edge id
    }
}
__global__ void k_count_q(const int* __restrict__ qu, int* __restrict__ cnt) {
    int j = blockIdx.x * blockDim.x + threadIdx.x;
    int st = gridDim.x * blockDim.x;
    for (; j < 2 * NQ; j += st)
        atomicAdd(&cnt[((j >= NQ) ? NEDGE : 0) + qu[2 * QROW + j]], 1);
}
__global__ void k_fill_q(const int* __restrict__ qu, int* __restrict__ cur,
                         int* __restrict__ list) {
    int j = blockIdx.x * blockDim.x + threadIdx.x;
    int st = gridDim.x * blockDim.x;
    for (; j < 2 * NQ; j += st) {
        int b = ((j >= NQ) ? NEDGE : 0) + qu[2 * QROW + j];
        int pos = atomicAdd(&cur[b], 1);
        list[pos] = j;                                  // GLOBAL qual id
    }
}

__global__ void k_dinv(const int* __restrict__ cnt, float* __restrict__ dinv) {
    int i = blockIdx.x * blockDim.x + threadIdx.x;
    int st = gridDim.x * blockDim.x;
    for (; i < 2 * NE; i += st) {
        int d = (i >= NE) ? 1 : 0;
        int n = i - d * NE;
        int c = cnt[(1 - d) * NE + n];     // deg(src,dir d) = dst counts of dir 1-d
        dinv[i] = (c > 0) ? rsqrtf((float)c) : 0.f;
    }
}

// ---------------- two-level exclusive scan ----------------------------------
__global__ void k_scan1(const int* __restrict__ in, int* __restrict__ out,
                        int* __restrict__ part, int n) {
    __shared__ int s[1024];
    int t = threadIdx.x;
    int g = blockIdx.x * 1024 + t;
    int v = (g < n) ? in[g] : 0;
    s[t] = v;
    __syncthreads();
    for (int off = 1; off < 1024; off <<= 1) {
        int u = (t >= off) ? s[t - off] : 0;
        __syncthreads();
        s[t] += u;
        __syncthreads();
    }
    if (g < n) out[g] = s[t] - v;
    if (t == 1023 && part) part[blockIdx.x] = s[1023];
}
__global__ void k_scan_add(int* __restrict__ out, const int* __restrict__ psc, int n) {
    int g = blockIdx.x * 1024 + threadIdx.x;
    if (g < n) out[g] += psc[blockIdx.x];
}

// ---------------- tf32 tensor-core GEMM -------------------------------------
// BM=64 rows/block, BK=40 per chunk, BN=200 (padded 208). 8 warps: 4xM, 2xN.

enum { M_QUAL = 0, M_FUSE = 1, M_WRITE = 2 };

#define BM 64
#define BK 40
#define AS_ST 44          // floats; 11 f4 per row (10 used)
#define WS_ST 216         // floats; 54 f4 per row (52 used)

__device__ __forceinline__ float tf32r(float x) {
    uint32_t u;
    asm("cvt.rna.tf32.f32 %0, %1;" : "=r"(u) : "f"(x));
    return __uint_as_float(u);
}
__device__ __forceinline__ float4 tf32r4(float4 v) {
    return make_float4(tf32r(v.x), tf32r(v.y), tf32r(v.z), tf32r(v.w));
}
__device__ __forceinline__ void mma8(float* c, const uint32_t* a,
                                     uint32_t b0, uint32_t b1) {
    asm volatile(
        "mma.sync.aligned.m16n8k8.row.col.f32.tf32.tf32.f32 "
        "{%0,%1,%2,%3}, {%4,%5,%6,%7}, {%8,%9}, {%0,%1,%2,%3};"
        : "+f"(c[0]), "+f"(c[1]), "+f"(c[2]), "+f"(c[3])
        : "r"(a[0]), "r"(a[1]), "r"(a[2]), "r"(a[3]), "r"(b0), "r"(b1));
}

// NCHUNK = K/40: 5 for QUAL/WRITE (K=200), 15 for FUSE (K=600)
template <int MODE, int NCHUNK>
__global__ void __launch_bounds__(256, 2)
k_gemm(const float* __restrict__ A,      // QUAL: x table | FUSE: nbuf_in | WRITE: rows
       const float* __restrict__ B2,     // FUSE: nbuf_out
       const float* __restrict__ C3,     // FUSE: x (loop section)
       const float* __restrict__ relt,   // QUAL: rel table | FUSE: loop_rel
       const int* __restrict__ qe, const int* __restrict__ qr,
       const float* __restrict__ W,      // QUAL: w_q | FUSE: w_in | WRITE: w_rel
       const float* __restrict__ W2,     // FUSE: w_out
       const float* __restrict__ W3,     // FUSE: w_loop
       float* __restrict__ out,
       const float* __restrict__ bias,   // FUSE
       int nrows)
{
    __shared__ float As[BM * AS_ST];
    __shared__ float Ws[BK * WS_ST];
    int tid = threadIdx.x;
    int wid = tid >> 5, lane = tid & 31;
    int wm = wid >> 1, wn = wid & 1;
    int r4 = lane >> 2, kq = lane & 3;
    int row0 = blockIdx.x * BM;

    float acc[13][4];
#pragma unroll
    for (int f = 0; f < 13; f++)
        acc[f][0] = acc[f][1] = acc[f][2] = acc[f][3] = 0.f;

    for (int ch = 0; ch < NCHUNK; ch++) {
        __syncthreads();
        // ---- A tile: 64 rows x 10 float4 ----
        for (int l = tid; l < BM * 10; l += 256) {
            int r = l / 10, k4 = l - r * 10;
            int gr = row0 + r;
            float4 v = make_float4(0.f, 0.f, 0.f, 0.f);
            if (gr < nrows) {
                if (MODE == M_QUAL) {
                    int g4 = ch * 10 + k4;
                    float4 xv = ((const float4*)(A + (size_t)qe[gr] * DIM))[g4];
                    float4 rv = ((const float4*)(relt + (size_t)qr[gr] * DIM))[g4];
                    v = make_float4(xv.x * rv.x, xv.y * rv.y, xv.z * rv.z, xv.w * rv.w);
                } else if (MODE == M_FUSE) {
                    int sec = ch / 5;
                    int l4 = (ch - sec * 5) * 10 + k4;
                    if (sec == 0)
                        v = ((const float4*)(A + (size_t)gr * DIM))[l4];
                    else if (sec == 1)
                        v = ((const float4*)(B2 + (size_t)gr * DIM))[l4];
                    else {
                        float4 xv = ((const float4*)(C3 + (size_t)gr * DIM))[l4];
                        float4 lr = ((const float4*)relt)[l4];
                        v = make_float4(xv.x * lr.x, xv.y * lr.y, xv.z * lr.z, xv.w * lr.w);
                    }
                } else {
                    v = ((const float4*)(A + (size_t)gr * DIM))[ch * 10 + k4];
                }
            }
            *(float4*)&As[r * AS_ST + k4 * 4] = tf32r4(v);
        }
        // ---- W tile: 40 rows x 52 float4 (50 real) ----
        for (int l = tid; l < BK * 52; l += 256) {
            int k = l / 52, n4 = l - k * 52;
            float4 v = make_float4(0.f, 0.f, 0.f, 0.f);
            if (n4 < D4) {
                const float* Wp;
                int wr;
                if (MODE == M_FUSE) {
                    int sec = ch / 5;
                    Wp = (sec == 0) ? W : (sec == 1) ? W2 : W3;
                    wr = (ch - sec * 5) * BK + k;
                } else {
                    Wp = W;
                    wr = ch * BK + k;
                }
                v = ((const float4*)(Wp + (size_t)wr * DIM))[n4];
            }
            *(float4*)&Ws[k * WS_ST + n4 * 4] = tf32r4(v);
        }
        __syncthreads();

#pragma unroll
        for (int k8 = 0; k8 < 5; k8++) {
            int k0 = k8 * 8;
            int rb = wm * 16 + r4;
            uint32_t a[4];
            a[0] = __float_as_uint(As[rb * AS_ST + k0 + kq]);
            a[1] = __float_as_uint(As[(rb + 8) * AS_ST + k0 + kq]);
            a[2] = __float_as_uint(As[rb * AS_ST + k0 + 4 + kq]);
            a[3] = __float_as_uint(As[(rb + 8) * AS_ST + k0 + 4 + kq]);
#pragma unroll
            for (int f = 0; f < 13; f++) {
                int nb = wn * 104 + 8 * f + r4;
                uint32_t b0 = __float_as_uint(Ws[(k0 + kq) * WS_ST + nb]);
                uint32_t b1 = __float_as_uint(Ws[(k0 + 4 + kq) * WS_ST + nb]);
                mma8(acc[f], a, b0, b1);
            }
        }
    }

    int gr0 = row0 + wm * 16 + r4;
#pragma unroll
    for (int f = 0; f < 13; f++) {
        int col = wn * 104 + 8 * f + 2 * kq;
        if (col >= DIM) continue;
#pragma unroll
        for (int half = 0; half < 2; half++) {
            int gr = gr0 + 8 * half;
            if (gr >= nrows) continue;
            size_t o = (size_t)gr * DIM + col;
            float v0 = acc[f][2 * half], v1 = acc[f][2 * half + 1];
            if (MODE == M_FUSE) {
                out[o]     = tanhf(v0 * (1.f / 3.f) + bias[col]);
                out[o + 1] = tanhf(v1 * (1.f / 3.f) + bias[col + 1]);
            } else {
                out[o] = v0; out[o + 1] = v1;
            }
        }
    }
}

// ---------------- CSR gather aggregation (both directions) -------------------
// warp w: d = w>=NE, node n. out = (d? nout : nin)[n]
__global__ void __launch_bounds__(256)
k_agg(const float* __restrict__ x, const float* __restrict__ relt,
      const float* __restrict__ dinv,
      const int* __restrict__ ei,      // src row base (2*NEDGE)
      const int* __restrict__ et,      // (2*NEDGE)
      const int* __restrict__ e_start, const int* __restrict__ e_cnt,
      const int* __restrict__ e_list,
      const int* __restrict__ q_start, const int* __restrict__ q_cnt,
      const int* __restrict__ q_list,
      const float* __restrict__ qproj,
      float* __restrict__ nin, float* __restrict__ nout)
{
    int w = (blockIdx.x * blockDim.x + threadIdx.x) >> 5;
    int lane = threadIdx.x & 31;
    if (w >= 2 * NE) return;
    int d = (w >= NE) ? 1 : 0;
    int n = w - d * NE;

    int c0 = lane;            // float4 index 0..49
    int c1 = lane + 32;
    bool has1 = (c1 < D4);

    float4 a0 = make_float4(0.f, 0.f, 0.f, 0.f);
    float4 a1 = a0;

    float dn = dinv[w];
    if (dn != 0.f) {
        const int* srcb = ei + (size_t)d * NEDGE;
        const int* etb  = et + (size_t)d * NEDGE;
        const int* qsb  = q_start + (size_t)d * NEDGE;
        const int* qcb  = q_cnt + (size_t)d * NEDGE;
        const float* dvb = dinv + (size_t)d * NE;
        int beg = e_start[w], cnt = e_cnt[w];
        for (int idx = beg; idx < beg + cnt; idx++) {
            int e = e_list[idx];
            int s = srcb[e], ty = etb[e];
            float nm = dn * dvb[s];
            const float4* xr = (const float4*)(x + (size_t)s * DIM);
            const float4* rr = (const float4*)(relt + (size_t)ty * DIM);
            float4 q0 = make_float4(0.f, 0.f, 0.f, 0.f);
            float4 q1 = q0;
            int qb = qsb[e], qc = qcb[e];
            for (int t = qb; t < qb + qc; t++) {
                const float4* qp = (const float4*)(qproj + (size_t)q_list[t] * DIM);
                float4 v0 = qp[c0];
                q0.x += v0.x; q0.y += v0.y; q0.z += v0.z; q0.w += v0.w;
                if (has1) {
                    float4 v1 = qp[c1];
                    q1.x += v1.x; q1.y += v1.y; q1.z += v1.z; q1.w += v1.w;
                }
            }
            float4 xv = xr[c0], rv = rr[c0];
            a0.x += nm * xv.x * (ALPHA * rv.x + (1.f - ALPHA) * q0.x);
            a0.y += nm * xv.y * (ALPHA * rv.y + (1.f - ALPHA) * q0.y);
            a0.z += nm * xv.z * (ALPHA * rv.z + (1.f - ALPHA) * q0.z);
            a0.w += nm * xv.w * (ALPHA * rv.w + (1.f - ALPHA) * q0.w);
            if (has1) {
                float4 xw = xr[c1], rw = rr[c1];
                a1.x += nm * xw.x * (ALPHA * rw.x + (1.f - ALPHA) * q1.x);
                a1.y += nm * xw.y * (ALPHA * rw.y + (1.f - ALPHA) * q1.y);
                a1.z += nm * xw.z * (ALPHA * rw.z + (1.f - ALPHA) * q1.z);
                a1.w += nm * xw.w * (ALPHA * rw.w + (1.f - ALPHA) * q1.w);
            }
        }
    }
    float4* ob = (float4*)((d ? nout : nin) + (size_t)n * DIM);
    ob[c0] = a0;
    if (has1) ob[c1] = a1;
}

// ---------------- final batched gathers --------------------------------------
__global__ void k_gather(const float* __restrict__ xf, const float* __restrict__ rf,
                         const int* __restrict__ ent_ix, const int* __restrict__ rel_ix,
                         const int* __restrict__ quals_ix, float* __restrict__ out)
{
    int warp = (blockIdx.x * blockDim.x + threadIdx.x) >> 5;
    int lane = threadIdx.x & 31;
    int nwarp = (gridDim.x * blockDim.x) >> 5;
    const int total = NB * 14;
    for (int r = warp; r < total; r += nwarp) {
        int b = r / 14, s = r - b * 14;
        const float* srcp;
        float* dstp;
        if (s == 0)      { srcp = xf + (size_t)ent_ix[b] * DIM;  dstp = out + OFF_SUB + (size_t)b * DIM; }
        else if (s == 1) { srcp = rf + (size_t)rel_ix[b] * DIM;  dstp = out + OFF_REL + (size_t)b * DIM; }
        else if (s < 8)  { int p = s - 2;
                           srcp = xf + (size_t)quals_ix[b * 2 * QP + 2 * p + 1] * DIM;
                           dstp = out + OFF_QO + ((size_t)b * QP + p) * DIM; }
        else             { int p = s - 8;
                           srcp = rf + (size_t)quals_ix[b * 2 * QP + 2 * p] * DIM;
                           dstp = out + OFF_QR + ((size_t)b * QP + p) * DIM; }
        for (int c = lane; c < D4; c += 32)
            ((float4*)dstp)[c] = ((const float4*)srcp)[c];
    }
}

// ---------------------------------------------------------------------------

extern "C" void kernel_launch(void* const* d_in, const int* in_sizes, int n_in,
                              void* d_out, int out_size)
{
    const float* ent        = (const float*)d_in[0];
    const float* rel0       = (const float*)d_in[1];
    const float* w_in[2]    = {(const float*)d_in[2],  (const float*)d_in[7]};
    const float* w_out[2]   = {(const float*)d_in[3],  (const float*)d_in[8]};
    const float* w_loop[2]  = {(const float*)d_in[4],  (const float*)d_in[9]};
    const float* w_rel[2]   = {(const float*)d_in[5],  (const float*)d_in[10]};
    const float* w_q[2]     = {(const float*)d_in[6],  (const float*)d_in[11]};
    const float* loop_rel[2]= {(const float*)d_in[12], (const float*)d_in[13]};
    const float* bias[2]    = {(const float*)d_in[14], (const float*)d_in[15]};
    const int* ei       = (const int*)d_in[16];
    const int* et       = (const int*)d_in[17];
    const int* qu       = (const int*)d_in[18];
    const int* ent_ix   = (const int*)d_in[19];
    const int* rel_ix   = (const int*)d_in[20];
    const int* quals_ix = (const int*)d_in[21];
    float* out = (float*)d_out;

    float *qproj, *nin, *nout, *x1, *r1, *dinv;
    int *ecnt, *estart, *ecur, *elist, *qcnt, *qstart, *qcur, *qlist, *part, *psc;
    cudaGetSymbolAddress((void**)&qproj,  g_qproj);
    cudaGetSymbolAddress((void**)&nin,    g_nin);
    cudaGetSymbolAddress((void**)&nout,   g_nout);
    cudaGetSymbolAddress((void**)&x1,     g_x1);
    cudaGetSymbolAddress((void**)&r1,     g_r1);
    cudaGetSymbolAddress((void**)&dinv,   g_dinv);
    cudaGetSymbolAddress((void**)&ecnt,   gi_ecnt);
    cudaGetSymbolAddress((void**)&estart, gi_estart);
    cudaGetSymbolAddress((void**)&ecur,   gi_ecur);
    cudaGetSymbolAddress((void**)&elist,  gi_elist);
    cudaGetSymbolAddress((void**)&qcnt,   gi_qcnt);
    cudaGetSymbolAddress((void**)&qstart, gi_qstart);
    cudaGetSymbolAddress((void**)&qcur,   gi_qcur);
    cudaGetSymbolAddress((void**)&qlist,  gi_qlist);
    cudaGetSymbolAddress((void**)&part,   gi_part);
    cudaGetSymbolAddress((void**)&psc,    gi_psc);

    // ---- CSR build ----
    k_zero<<<256, 256>>>((float*)ecnt, 2L * NE);
    k_zero<<<512, 256>>>((float*)qcnt, 2L * NEDGE);
    k_count_e<<<2048, 256>>>(ei, ecnt);
    k_count_q<<<2048, 256>>>(qu, qcnt);

    int nbE = (2 * NE + 1023) / 1024;
    k_scan1<<<nbE, 1024>>>(ecnt, estart, part, 2 * NE);
    k_scan1<<<1, 1024>>>(part, psc, (int*)0, nbE);
    k_scan_add<<<nbE, 1024>>>(estart, psc, 2 * NE);
    cudaMemcpyAsync(ecur, estart, 2L * NE * sizeof(int), cudaMemcpyDeviceToDevice, 0);
    k_fill_e<<<2048, 256>>>(ei, ecur, elist);

    int nbQ = (2 * NEDGE + 1023) / 1024;
    k_scan1<<<nbQ, 1024>>>(qcnt, qstart, part, 2 * NEDGE);
    k_scan1<<<1, 1024>>>(part, psc, (int*)0, nbQ);
    k_scan_add<<<nbQ, 1024>>>(qstart, psc, 2 * NEDGE);
    cudaMemcpyAsync(qcur, qstart, 2L * NEDGE * sizeof(int), cudaMemcpyDeviceToDevice, 0);
    k_fill_q<<<2048, 256>>>(qu, qcur, qlist);

    k_dinv<<<512, 256>>>(ecnt, dinv);

    float* xf = out + OFF_X;
    float* rf = out + OFF_R;

    for (int L = 0; L < 2; L++) {
        const float* xin = L ? (const float*)x1 : ent;
        const float* rin = L ? (const float*)r1 : rel0;
        float* xout = L ? xf : x1;
        float* rout = L ? rf : r1;

        // qproj[j] = (x[q_e[j]] ⊙ rel[q_r[j]]) @ w_q   for ALL 800k quals
        k_gemm<M_QUAL, 5><<<(QROW + BM - 1) / BM, 256>>>(
            xin, 0, 0, rin,
            qu + QROW,       // q_e (row 1, both dirs)
            qu,              // q_r (row 0, both dirs)
            w_q[L], 0, 0, qproj, 0, QROW);

        // both-direction CSR gather -> nin / nout
        k_agg<<<(2 * NE * 32 + 255) / 256, 256>>>(
            xin, rin, dinv, ei, et,
            estart, ecnt, elist, qstart, qcnt, qlist, qproj, nin, nout);

        // x_out = tanh(([nin|nout|x⊙loop] @ [w_in;w_out;w_loop])/3 + b)
        k_gemm<M_FUSE, 15><<<(NE + BM - 1) / BM, 256>>>(
            nin, nout, xin, loop_rel[L], 0, 0,
            w_in[L], w_out[L], w_loop[L], xout, bias[L], NE);

        // r_out = r_in @ w_rel
        k_gemm<M_WRITE, 5><<<(NR + BM - 1) / BM, 256>>>(
            rin, 0, 0, 0, 0, 0, w_rel[L], 0, 0, rout, 0, NR);
    }

    k_gather<<<7168, 256>>>(xf, rf, ent_ix, rel_ix, quals_ix, out);
}

// round 9
// speedup vs baseline: 4.1780x; 1.3476x over previous
#include <cuda_runtime.h>
#include <cuda_fp16.h>
#include <math.h>
#include <stdint.h>

// ---------------------------------------------------------------------------
// HypRelEncoder — round 8 (bisect: fp16 MMA kept, cp.async REMOVED):
//  * fp16 mma.m16n8k16 GEMMs (ldmatrix A + ldmatrix.trans B), fp32 accum
//  * full-K A tile loaded once per block (1 DRAM touch per gathered row)
//  * W streamed 16-k chunks via REGISTER staging (LDG next overlaps MMA cur)
//  * CSR aggregation / build / gathers unchanged from round 5 (proven)
// ---------------------------------------------------------------------------

#define NE    200000
#define DIM   200
#define D4    50          // DIM / 4
#define NEDGE 500000
#define NQ    400000
#define QROW  (2*NQ)      // 800000
#define NR    200
#define NB    4096
#define QP    6
#define ALPHA 0.8f
#define MSZ   (208*208)   // padded fp16 weight matrix size

#define OFF_SUB 0
#define OFF_REL (NB*DIM)
#define OFF_QO  (2*NB*DIM)
#define OFF_QR  (OFF_QO + NB*QP*DIM)
#define OFF_X   (OFF_QR + NB*QP*DIM)
#define OFF_R   (OFF_X + NE*DIM)

// ---------------- device scratch -------------------------------------------
__device__ float g_qproj[(size_t)QROW * DIM];    // 640 MB
__device__ float g_nin [(size_t)NE * DIM];
__device__ float g_nout[(size_t)NE * DIM];
__device__ float g_x1  [(size_t)NE * DIM];
__device__ float g_r1[NR * DIM];
__device__ float g_dinv[2 * NE];
__device__ __align__(16) __half g_wh[(size_t)10 * MSZ];   // padded fp16 weights
__device__ int gi_ecnt[2 * NE];
__device__ int gi_estart[2 * NE];
__device__ int gi_ecur[2 * NE];
__device__ int gi_elist[2 * NEDGE];
__device__ int gi_qcnt[2 * NEDGE];
__device__ int gi_qstart[2 * NEDGE];
__device__ int gi_qcur[2 * NEDGE];
__device__ int gi_qlist[2 * NQ];
__device__ int gi_part[1024];
__device__ int gi_psc[1024];

// ---------------- small helpers --------------------------------------------
__global__ void k_zero(float* __restrict__ p, long n) {
    long i = ((long)blockIdx.x * blockDim.x + threadIdx.x) * 4;
    long st = (long)gridDim.x * blockDim.x * 4;
    float4 z = make_float4(0.f, 0.f, 0.f, 0.f);
    for (; i < n; i += st) *(float4*)(p + i) = z;
}

__global__ void k_count_e(const int* __restrict__ ei, int* __restrict__ cnt) {
    int i = blockIdx.x * blockDim.x + threadIdx.x;
    int st = gridDim.x * blockDim.x;
    for (; i < 2 * NEDGE; i += st)
        atomicAdd(&cnt[((i >= NEDGE) ? NE : 0) + ei[2 * NEDGE + i]], 1);
}
__global__ void k_fill_e(const int* __restrict__ ei, int* __restrict__ cur,
                         int* __restrict__ list) {
    int i = blockIdx.x * blockDim.x + threadIdx.x;
    int st = gridDim.x * blockDim.x;
    for (; i < 2 * NEDGE; i += st) {
        int b = ((i >= NEDGE) ? NE : 0) + ei[2 * NEDGE + i];
        int pos = atomicAdd(&cur[b], 1);
        list[pos] = (i >= NEDGE) ? i - NEDGE : i;
    }
}
__global__ void k_count_q(const int* __restrict__ qu, int* __restrict__ cnt) {
    int j = blockIdx.x * blockDim.x + threadIdx.x;
    int st = gridDim.x * blockDim.x;
    for (; j < 2 * NQ; j += st)
        atomicAdd(&cnt[((j >= NQ) ? NEDGE : 0) + qu[2 * QROW + j]], 1);
}
__global__ void k_fill_q(const int* __restrict__ qu, int* __restrict__ cur,
                         int* __restrict__ list) {
    int j = blockIdx.x * blockDim.x + threadIdx.x;
    int st = gridDim.x * blockDim.x;
    for (; j < 2 * NQ; j += st) {
        int b = ((j >= NQ) ? NEDGE : 0) + qu[2 * QROW + j];
        int pos = atomicAdd(&cur[b], 1);
        list[pos] = j;          // GLOBAL qual id
    }
}
__global__ void k_dinv(const int* __restrict__ cnt, float* __restrict__ dinv) {
    int i = blockIdx.x * blockDim.x + threadIdx.x;
    int st = gridDim.x * blockDim.x;
    for (; i < 2 * NE; i += st) {
        int d = (i >= NE) ? 1 : 0;
        int n = i - d * NE;
        int c = cnt[(1 - d) * NE + n];
        dinv[i] = (c > 0) ? rsqrtf((float)c) : 0.f;
    }
}

// W fp32 [200][200] -> fp16 zero-padded [208][208]
__global__ void k_convW(const float* __restrict__ W, __half* __restrict__ dst) {
    int t = blockIdx.x * blockDim.x + threadIdx.x;
    if (t >= MSZ) return;
    int k = t / 208, n = t - k * 208;
    float v = (k < DIM && n < DIM) ? W[k * DIM + n] : 0.f;
    dst[t] = __float2half_rn(v);
}

// ---------------- two-level exclusive scan ----------------------------------
__global__ void k_scan1(const int* __restrict__ in, int* __restrict__ out,
                        int* __restrict__ part, int n) {
    __shared__ int s[1024];
    int t = threadIdx.x;
    int g = blockIdx.x * 1024 + t;
    int v = (g < n) ? in[g] : 0;
    s[t] = v;
    __syncthreads();
    for (int off = 1; off < 1024; off <<= 1) {
        int u = (t >= off) ? s[t - off] : 0;
        __syncthreads();
        s[t] += u;
        __syncthreads();
    }
    if (g < n) out[g] = s[t] - v;
    if (t == 1023 && part) part[blockIdx.x] = s[1023];
}
__global__ void k_scan_add(int* __restrict__ out, const int* __restrict__ psc, int n) {
    int g = blockIdx.x * 1024 + threadIdx.x;
    if (g < n) out[g] += psc[blockIdx.x];
}

// ---------------- fp16 tensor-core GEMM --------------------------------------
// C[rows,200] = compose(A)[rows,K] @ W[K,200]; K processed as sections of 200.
// BM=64, 8 warps (4xM, 2xN); full-K A tile in smem; W reg-staged k16 chunks.

enum { M_QUAL = 0, M_FUSE = 1, M_PLAIN = 2 };

#define BM  64
#define AST 216       // half stride (432B = 27*16)
#define WST 216

__device__ __forceinline__ uint32_t s2u(const void* p) {
    return (uint32_t)__cvta_generic_to_shared(p);
}
__device__ __forceinline__ void mma16(float* c, uint32_t a0, uint32_t a1,
                                      uint32_t a2, uint32_t a3,
                                      uint32_t b0, uint32_t b1) {
    asm volatile(
        "mma.sync.aligned.m16n8k16.row.col.f32.f16.f16.f32 "
        "{%0,%1,%2,%3},{%4,%5,%6,%7},{%8,%9},{%0,%1,%2,%3};"
        : "+f"(c[0]), "+f"(c[1]), "+f"(c[2]), "+f"(c[3])
        : "r"(a0), "r"(a1), "r"(a2), "r"(a3), "r"(b0), "r"(b1));
}

template <int MODE>
__global__ void __launch_bounds__(256, 2)
k_gemm(const float* __restrict__ A,      // QUAL: x table | FUSE: nin | PLAIN: rows
       const float* __restrict__ B2,     // FUSE: nout
       const float* __restrict__ C3,     // FUSE: x (loop section)
       const float* __restrict__ relt,   // QUAL: rel table | FUSE: loop_rel
       const int* __restrict__ qe, const int* __restrict__ qr,
       const __half* __restrict__ Wh,    // fp16 padded; FUSE: 3 consecutive
       float* __restrict__ out,
       const float* __restrict__ bias,   // FUSE
       int nrows)
{
    __shared__ __align__(16) __half As[BM * AST];
    __shared__ __align__(16) __half Wb[16 * WST];
    const int tid = threadIdx.x;
    const int wid = tid >> 5, lane = tid & 31;
    const int wm = wid >> 1, wn = wid & 1;
    const int r4 = lane >> 2, kq = lane & 3;
    const int row0 = blockIdx.x * BM;
    const int NSEC = (MODE == M_FUSE) ? 3 : 1;
    // W chunk = 16 rows x 208 halfs = 416 contiguous uint4; thread handles
    // segment tid and (tid<160) tid+256.
    const int k0a = tid / 26, sg0 = tid - k0a * 26;
    const int s1 = tid + 256;
    const int k1a = s1 / 26, sg1 = s1 - k1a * 26;
    const bool h2nd = (tid < 160);

    float acc[13][4];
#pragma unroll
    for (int f = 0; f < 13; f++)
        acc[f][0] = acc[f][1] = acc[f][2] = acc[f][3] = 0.f;

    for (int sec = 0; sec < NSEC; sec++) {
        __syncthreads();   // prev section's MMA reads of As complete
        // ---- fill full-K A tile (fp16), warp-per-row ----
        for (int rr = wid; rr < BM; rr += 8) {
            int gr = row0 + rr;
            const float4 *p1 = 0, *p2 = 0;
            bool valid = gr < nrows;
            if (valid) {
                if (MODE == M_QUAL) {
                    p1 = (const float4*)(A + (size_t)qe[gr] * DIM);
                    p2 = (const float4*)(relt + (size_t)qr[gr] * DIM);
                } else if (MODE == M_FUSE) {
                    if (sec == 0)      p1 = (const float4*)(A  + (size_t)gr * DIM);
                    else if (sec == 1) p1 = (const float4*)(B2 + (size_t)gr * DIM);
                    else { p1 = (const float4*)(C3 + (size_t)gr * DIM);
                           p2 = (const float4*)relt; }
                } else {
                    p1 = (const float4*)(A + (size_t)gr * DIM);
                }
            }
#pragma unroll
            for (int h = 0; h < 2; h++) {
                int k4 = lane + 32 * h;
                if (k4 >= 54) continue;              // 54*4 = 216 = AST (pad zeros)
                float4 v = make_float4(0.f, 0.f, 0.f, 0.f);
                if (valid && k4 < D4) {
                    v = p1[k4];
                    if (MODE == M_QUAL || (MODE == M_FUSE && sec == 2)) {
                        float4 r = p2[k4];
                        v.x *= r.x; v.y *= r.y; v.z *= r.z; v.w *= r.w;
                    }
                }
                union { uint2 u; __half2 h2[2]; } pk;
                pk.h2[0] = __floats2half2_rn(v.x, v.y);
                pk.h2[1] = __floats2half2_rn(v.z, v.w);
                *reinterpret_cast<uint2*>(&As[rr * AST + k4 * 4]) = pk.u;
            }
        }
        const __half* Wg = Wh + (size_t)sec * MSZ;

        // preload W chunk 0 into registers (L2-resident after first block)
        uint4 w0 = ((const uint4*)Wg)[tid];
        uint4 w1 = h2nd ? ((const uint4*)Wg)[s1] : make_uint4(0, 0, 0, 0);

        for (int ks = 0; ks < 13; ks++) {
            __syncthreads();        // prior chunk's ldmatrix reads of Wb done
            *(uint4*)&Wb[k0a * WST + sg0 * 8] = w0;
            if (h2nd) *(uint4*)&Wb[k1a * WST + sg1 * 8] = w1;
            if (ks < 12) {          // issue next-chunk LDG; overlaps MMA below
                const uint4* src = (const uint4*)(Wg + (size_t)(ks + 1) * 16 * 208);
                w0 = src[tid];
                if (h2nd) w1 = src[s1];
            }
            __syncthreads();        // Wb (and As on ks==0) visible

            uint32_t a0, a1, a2, a3;
            uint32_t aaddr = s2u(&As[(wm * 16 + (lane & 15)) * AST
                                     + ks * 16 + ((lane >> 4) << 3)]);
            asm volatile("ldmatrix.sync.aligned.m8n8.x4.shared.b16 {%0,%1,%2,%3}, [%4];"
                         : "=r"(a0), "=r"(a1), "=r"(a2), "=r"(a3) : "r"(aaddr));
            int brow = ((lane >> 3) & 1) * 8 + (lane & 7);
#pragma unroll
            for (int fp = 0; fp < 6; fp++) {
                int n0 = wn * 104 + fp * 16;
                uint32_t b0, b1, b2, b3;
                uint32_t baddr = s2u(&Wb[brow * WST + n0 + ((lane >> 4) << 3)]);
                asm volatile("ldmatrix.sync.aligned.m8n8.x4.trans.shared.b16 "
                             "{%0,%1,%2,%3}, [%4];"
                             : "=r"(b0), "=r"(b1), "=r"(b2), "=r"(b3) : "r"(baddr));
                mma16(acc[2 * fp], a0, a1, a2, a3, b0, b1);
                mma16(acc[2 * fp + 1], a0, a1, a2, a3, b2, b3);
            }
            {
                int n0 = wn * 104 + 96;
                uint32_t b0, b1;
                uint32_t baddr = s2u(&Wb[brow * WST + n0]);
                asm volatile("ldmatrix.sync.aligned.m8n8.x2.trans.shared.b16 "
                             "{%0,%1}, [%2];"
                             : "=r"(b0), "=r"(b1) : "r"(baddr));
                mma16(acc[12], a0, a1, a2, a3, b0, b1);
            }
        }
    }

    // ---- epilogue ----
    int gr0 = row0 + wm * 16 + r4;
#pragma unroll
    for (int f = 0; f < 13; f++) {
        int col = wn * 104 + 8 * f + 2 * kq;
        if (col >= DIM) continue;
#pragma unroll
        for (int half = 0; half < 2; half++) {
            int gr = gr0 + 8 * half;
            if (gr >= nrows) continue;
            size_t o = (size_t)gr * DIM + col;
            float v0 = acc[f][2 * half], v1 = acc[f][2 * half + 1];
            if (MODE == M_FUSE) {
                out[o]     = tanhf(v0 * (1.f / 3.f) + bias[col]);
                out[o + 1] = tanhf(v1 * (1.f / 3.f) + bias[col + 1]);
            } else {
                out[o] = v0; out[o + 1] = v1;
            }
        }
    }
}

// ---------------- CSR gather aggregation (both directions) -------------------
__global__ void __launch_bounds__(256)
k_agg(const float* __restrict__ x, const float* __restrict__ relt,
      const float* __restrict__ dinv,
      const int* __restrict__ ei, const int* __restrict__ et,
      const int* __restrict__ e_start, const int* __restrict__ e_cnt,
      const int* __restrict__ e_list,
      const int* __restrict__ q_start, const int* __restrict__ q_cnt,
      const int* __restrict__ q_list,
      const float* __restrict__ qproj,
      float* __restrict__ nin, float* __restrict__ nout)
{
    int w = (blockIdx.x * blockDim.x + threadIdx.x) >> 5;
    int lane = threadIdx.x & 31;
    if (w >= 2 * NE) return;
    int d = (w >= NE) ? 1 : 0;
    int n = w - d * NE;

    int c0 = lane;
    int c1 = lane + 32;
    bool has1 = (c1 < D4);

    float4 a0 = make_float4(0.f, 0.f, 0.f, 0.f);
    float4 a1 = a0;

    float dn = dinv[w];
    if (dn != 0.f) {
        const int* srcb = ei + (size_t)d * NEDGE;
        const int* etb  = et + (size_t)d * NEDGE;
        const int* qsb  = q_start + (size_t)d * NEDGE;
        const int* qcb  = q_cnt + (size_t)d * NEDGE;
        const float* dvb = dinv + (size_t)d * NE;
        int beg = e_start[w], cnt = e_cnt[w];
        for (int idx = beg; idx < beg + cnt; idx++) {
            int e = e_list[idx];
            int s = srcb[e], ty = etb[e];
            float nm = dn * dvb[s];
            const float4* xr = (const float4*)(x + (size_t)s * DIM);
            const float4* rr = (const float4*)(relt + (size_t)ty * DIM);
            float4 q0 = make_float4(0.f, 0.f, 0.f, 0.f);
            float4 q1 = q0;
            int qb = qsb[e], qc = qcb[e];
            for (int t = qb; t < qb + qc; t++) {
                const float4* qp = (const float4*)(qproj + (size_t)q_list[t] * DIM);
                float4 v0 = qp[c0];
                q0.x += v0.x; q0.y += v0.y; q0.z += v0.z; q0.w += v0.w;
                if (has1) {
                    float4 v1 = qp[c1];
                    q1.x += v1.x; q1.y += v1.y; q1.z += v1.z; q1.w += v1.w;
                }
            }
            float4 xv = xr[c0], rv = rr[c0];
            a0.x += nm * xv.x * (ALPHA * rv.x + (1.f - ALPHA) * q0.x);
            a0.y += nm * xv.y * (ALPHA * rv.y + (1.f - ALPHA) * q0.y);
            a0.z += nm * xv.z * (ALPHA * rv.z + (1.f - ALPHA) * q0.z);
            a0.w += nm * xv.w * (ALPHA * rv.w + (1.f - ALPHA) * q0.w);
            if (has1) {
                float4 xw = xr[c1], rw = rr[c1];
                a1.x += nm * xw.x * (ALPHA * rw.x + (1.f - ALPHA) * q1.x);
                a1.y += nm * xw.y * (ALPHA * rw.y + (1.f - ALPHA) * q1.y);
                a1.z += nm * xw.z * (ALPHA * rw.z + (1.f - ALPHA) * q1.z);
                a1.w += nm * xw.w * (ALPHA * rw.w + (1.f - ALPHA) * q1.w);
            }
        }
    }
    float4* ob = (float4*)((d ? nout : nin) + (size_t)n * DIM);
    ob[c0] = a0;
    if (has1) ob[c1] = a1;
}

// ---------------- final batched gathers --------------------------------------
__global__ void k_gather(const float* __restrict__ xf, const float* __restrict__ rf,
                         const int* __restrict__ ent_ix, const int* __restrict__ rel_ix,
                         const int* __restrict__ quals_ix, float* __restrict__ out)
{
    int warp = (blockIdx.x * blockDim.x + threadIdx.x) >> 5;
    int lane = threadIdx.x & 31;
    int nwarp = (gridDim.x * blockDim.x) >> 5;
    const int total = NB * 14;
    for (int r = warp; r < total; r += nwarp) {
        int b = r / 14, s = r - b * 14;
        const float* srcp;
        float* dstp;
        if (s == 0)      { srcp = xf + (size_t)ent_ix[b] * DIM;  dstp = out + OFF_SUB + (size_t)b * DIM; }
        else if (s == 1) { srcp = rf + (size_t)rel_ix[b] * DIM;  dstp = out + OFF_REL + (size_t)b * DIM; }
        else if (s < 8)  { int p = s - 2;
                           srcp = xf + (size_t)quals_ix[b * 2 * QP + 2 * p + 1] * DIM;
                           dstp = out + OFF_QO + ((size_t)b * QP + p) * DIM; }
        else             { int p = s - 8;
                           srcp = rf + (size_t)quals_ix[b * 2 * QP + 2 * p] * DIM;
                           dstp = out + OFF_QR + ((size_t)b * QP + p) * DIM; }
        for (int c = lane; c < D4; c += 32)
            ((float4*)dstp)[c] = ((const float4*)srcp)[c];
    }
}

// ---------------------------------------------------------------------------

extern "C" void kernel_launch(void* const* d_in, const int* in_sizes, int n_in,
                              void* d_out, int out_size)
{
    const float* ent        = (const float*)d_in[0];
    const float* rel0       = (const float*)d_in[1];
    const float* w_in[2]    = {(const float*)d_in[2],  (const float*)d_in[7]};
    const float* w_out[2]   = {(const float*)d_in[3],  (const float*)d_in[8]};
    const float* w_loop[2]  = {(const float*)d_in[4],  (const float*)d_in[9]};
    const float* w_rel[2]   = {(const float*)d_in[5],  (const float*)d_in[10]};
    const float* w_q[2]     = {(const float*)d_in[6],  (const float*)d_in[11]};
    const float* loop_rel[2]= {(const float*)d_in[12], (const float*)d_in[13]};
    const float* bias[2]    = {(const float*)d_in[14], (const float*)d_in[15]};
    const int* ei       = (const int*)d_in[16];
    const int* et       = (const int*)d_in[17];
    const int* qu       = (const int*)d_in[18];
    const int* ent_ix   = (const int*)d_in[19];
    const int* rel_ix   = (const int*)d_in[20];
    const int* quals_ix = (const int*)d_in[21];
    float* out = (float*)d_out;

    float *qproj, *nin, *nout, *x1, *r1, *dinv;
    __half* wh;
    int *ecnt, *estart, *ecur, *elist, *qcnt, *qstart, *qcur, *qlist, *part, *psc;
    cudaGetSymbolAddress((void**)&qproj,  g_qproj);
    cudaGetSymbolAddress((void**)&nin,    g_nin);
    cudaGetSymbolAddress((void**)&nout,   g_nout);
    cudaGetSymbolAddress((void**)&x1,     g_x1);
    cudaGetSymbolAddress((void**)&r1,     g_r1);
    cudaGetSymbolAddress((void**)&dinv,   g_dinv);
    cudaGetSymbolAddress((void**)&wh,     g_wh);
    cudaGetSymbolAddress((void**)&ecnt,   gi_ecnt);
    cudaGetSymbolAddress((void**)&estart, gi_estart);
    cudaGetSymbolAddress((void**)&ecur,   gi_ecur);
    cudaGetSymbolAddress((void**)&elist,  gi_elist);
    cudaGetSymbolAddress((void**)&qcnt,   gi_qcnt);
    cudaGetSymbolAddress((void**)&qstart, gi_qstart);
    cudaGetSymbolAddress((void**)&qcur,   gi_qcur);
    cudaGetSymbolAddress((void**)&qlist,  gi_qlist);
    cudaGetSymbolAddress((void**)&part,   gi_part);
    cudaGetSymbolAddress((void**)&psc,    gi_psc);

    // ---- fp16 weight conversion: order per layer {w_in,w_out,w_loop,w_q,w_rel}
    int cb = (MSZ + 255) / 256;
    for (int L = 0; L < 2; L++) {
        k_convW<<<cb, 256>>>(w_in[L],   wh + (size_t)(L * 5 + 0) * MSZ);
        k_convW<<<cb, 256>>>(w_out[L],  wh + (size_t)(L * 5 + 1) * MSZ);
        k_convW<<<cb, 256>>>(w_loop[L], wh + (size_t)(L * 5 + 2) * MSZ);
        k_convW<<<cb, 256>>>(w_q[L],    wh + (size_t)(L * 5 + 3) * MSZ);
        k_convW<<<cb, 256>>>(w_rel[L],  wh + (size_t)(L * 5 + 4) * MSZ);
    }

    // ---- CSR build ----
    k_zero<<<256, 256>>>((float*)ecnt, 2L * NE);
    k_zero<<<512, 256>>>((float*)qcnt, 2L * NEDGE);
    k_count_e<<<2048, 256>>>(ei, ecnt);
    k_count_q<<<2048, 256>>>(qu, qcnt);

    int nbE = (2 * NE + 1023) / 1024;
    k_scan1<<<nbE, 1024>>>(ecnt, estart, part, 2 * NE);
    k_scan1<<<1, 1024>>>(part, psc, (int*)0, nbE);
    k_scan_add<<<nbE, 1024>>>(estart, psc, 2 * NE);
    cudaMemcpyAsync(ecur, estart, 2L * NE * sizeof(int), cudaMemcpyDeviceToDevice, 0);
    k_fill_e<<<2048, 256>>>(ei, ecur, elist);

    int nbQ = (2 * NEDGE + 1023) / 1024;
    k_scan1<<<nbQ, 1024>>>(qcnt, qstart, part, 2 * NEDGE);
    k_scan1<<<1, 1024>>>(part, psc, (int*)0, nbQ);
    k_scan_add<<<nbQ, 1024>>>(qstart, psc, 2 * NEDGE);
    cudaMemcpyAsync(qcur, qstart, 2L * NEDGE * sizeof(int), cudaMemcpyDeviceToDevice, 0);
    k_fill_q<<<2048, 256>>>(qu, qcur, qlist);

    k_dinv<<<512, 256>>>(ecnt, dinv);

    float* xf = out + OFF_X;
    float* rf = out + OFF_R;

    for (int L = 0; L < 2; L++) {
        const float* xin = L ? (const float*)x1 : ent;
        const float* rin = L ? (const float*)r1 : rel0;
        float* xout = L ? xf : x1;
        float* rout = L ? rf : r1;

        // qproj[j] = (x[q_e[j]] ⊙ rel[q_r[j]]) @ w_q   (800k rows)
        k_gemm<M_QUAL><<<(QROW + BM - 1) / BM, 256>>>(
            xin, 0, 0, rin, qu + QROW, qu,
            wh + (size_t)(L * 5 + 3) * MSZ, qproj, 0, QROW);

        // both-direction CSR gather -> nin / nout
        k_agg<<<(2 * NE * 32 + 255) / 256, 256>>>(
            xin, rin, dinv, ei, et,
            estart, ecnt, elist, qstart, qcnt, qlist, qproj, nin, nout);

        // x_out = tanh(([nin|nout|x⊙loop] @ [w_in;w_out;w_loop])/3 + b)
        k_gemm<M_FUSE><<<(NE + BM - 1) / BM, 256>>>(
            nin, nout, xin, loop_rel[L], 0, 0,
            wh + (size_t)(L * 5 + 0) * MSZ, xout, bias[L], NE);

        // r_out = r_in @ w_rel
        k_gemm<M_PLAIN><<<(NR + BM - 1) / BM, 256>>>(
            rin, 0, 0, 0, 0, 0,
            wh + (size_t)(L * 5 + 4) * MSZ, rout, 0, NR);
    }

    k_gather<<<7168, 256>>>(xf, rf, ent_ix, rel_ix, quals_ix, out);
}